// round 16
// baseline (speedup 1.0000x reference)
#include <cuda_runtime.h>
#include <cuda_bf16.h>
#include <cuda_fp16.h>
#include <math.h>
#include <stdint.h>

// ---------------- problem constants ----------------
constexpr int cB = 2, cS = 2048, cV = 32000, cE = 512, cH = 8, cL = 4;
constexpr int cDH = 64, cM = 256, cCHUNK = 128;
constexpr int cBS = cB * cS;
constexpr int cBH = cB * cH;
constexpr int cNC = cS / cCHUNK;

// ---------------- float scratch ----------------
constexpr size_t OFF_X    = 0;
constexpr size_t OFF_KD   = OFF_X + (size_t)cBS * cE;
constexpr size_t OFF_KV   = OFF_KD + (size_t)cBH * cS;
constexpr size_t OFF_ZC   = OFF_KV + (size_t)cBH * cNC * cM * cDH;
constexpr size_t OFF_GMAX = OFF_ZC + (size_t)cBH * cNC * cM;
constexpr size_t SCRATCH_FLOATS = OFF_GMAX + 64;

__device__ float g_scratch[SCRATCH_FLOATS];

// ---------------- half scratch ----------------
constexpr size_t HOFF_H   = 0;
constexpr size_t HOFF_O   = HOFF_H + (size_t)cBS * cE;
constexpr size_t HOFF_FFN = HOFF_O + (size_t)cBS * cE;
constexpr size_t HOFF_XH  = HOFF_FFN + (size_t)cBS * 4 * cE;
constexpr size_t HOFF_VH  = HOFF_XH + (size_t)cBS * cE;
constexpr size_t HOFF_QH  = HOFF_VH + (size_t)cBS * cE;
constexpr size_t HOFF_KH  = HOFF_QH + (size_t)cBS * cE;
constexpr size_t HOFF_QFH = HOFF_KH + (size_t)cBS * cE;
constexpr size_t HOFF_KFH = HOFF_QFH + (size_t)cBH * cS * cM;
constexpr size_t HOFF_SPH = HOFF_KFH + (size_t)cBH * cS * cM;      // [bh][c][m][72]
constexpr size_t HOFF_PJ  = HOFF_SPH + (size_t)cBH * cNC * cM * 72;
constexpr size_t HOFF_WQ  = HOFF_PJ + (size_t)cL * cM * cDH;
constexpr size_t HOFF_WK  = HOFF_WQ + (size_t)cL * cE * cE;
constexpr size_t HOFF_WV  = HOFF_WK + (size_t)cL * cE * cE;
constexpr size_t HOFF_WO  = HOFF_WV + (size_t)cL * cE * cE;
constexpr size_t HOFF_W1  = HOFF_WO + (size_t)cL * cE * cE;
constexpr size_t HOFF_W2  = HOFF_W1 + (size_t)cL * cE * 4 * cE;
constexpr size_t HOFF_FCW = HOFF_W2 + (size_t)cL * cE * 4 * cE;
constexpr size_t SCRATCH_HALVES = HOFF_FCW + (size_t)cE * cV;

__device__ __half g_scratch_h[SCRATCH_HALVES];

// ---------------- helpers ----------------
__device__ __forceinline__ void atomicMaxFloat(float* addr, float value) {
    if (value >= 0.f) atomicMax((int*)addr, __float_as_int(value));
    else              atomicMin((unsigned int*)addr, __float_as_uint(value));
}

__device__ __forceinline__ void mma_f16(float* c, const unsigned* a, unsigned b0, unsigned b1) {
    asm volatile("mma.sync.aligned.m16n8k16.row.col.f32.f16.f16.f32 "
        "{%0,%1,%2,%3}, {%4,%5,%6,%7}, {%8,%9}, {%0,%1,%2,%3};"
        : "+f"(c[0]), "+f"(c[1]), "+f"(c[2]), "+f"(c[3])
        : "r"(a[0]), "r"(a[1]), "r"(a[2]), "r"(a[3]), "r"(b0), "r"(b1));
}

__device__ __forceinline__ void ldsm_x4(unsigned& r0, unsigned& r1, unsigned& r2, unsigned& r3,
                                        unsigned addr) {
    asm volatile("ldmatrix.sync.aligned.m8n8.x4.shared.b16 {%0,%1,%2,%3}, [%4];"
        : "=r"(r0), "=r"(r1), "=r"(r2), "=r"(r3) : "r"(addr));
}
__device__ __forceinline__ void ldsm_x4t(unsigned& r0, unsigned& r1, unsigned& r2, unsigned& r3,
                                         unsigned addr) {
    asm volatile("ldmatrix.sync.aligned.m8n8.x4.trans.shared.b16 {%0,%1,%2,%3}, [%4];"
        : "=r"(r0), "=r"(r1), "=r"(r2), "=r"(r3) : "r"(addr));
}
__device__ __forceinline__ void ldsm_x2t(unsigned& r0, unsigned& r1, unsigned addr) {
    asm volatile("ldmatrix.sync.aligned.m8n8.x2.trans.shared.b16 {%0,%1}, [%2];"
        : "=r"(r0), "=r"(r1) : "r"(addr));
}

__device__ __forceinline__ void cp16(unsigned dst, const void* src) {
    asm volatile("cp.async.cg.shared.global [%0], [%1], 16;" :: "r"(dst), "l"(src));
}
__device__ __forceinline__ void cp_commit() { asm volatile("cp.async.commit_group;"); }
template<int n> __device__ __forceinline__ void cp_wait() {
    asm volatile("cp.async.wait_group %0;" :: "n"(n));
}

__device__ __forceinline__ float warp_sum(float v) {
#pragma unroll
    for (int s = 16; s > 0; s >>= 1) v += __shfl_xor_sync(0xffffffff, v, s);
    return v;
}

// ---------------- fp32 -> fp16 converts (batched) ----------------
__global__ void f2h4_kernel(const float* __restrict__ s0, const float* __restrict__ s1,
                            const float* __restrict__ s2, const float* __restrict__ s3,
                            __half* __restrict__ d0, __half* __restrict__ d1,
                            __half* __restrict__ d2, __half* __restrict__ d3, int n4)
{
    int sel = blockIdx.y;
    const float* in = sel == 0 ? s0 : (sel == 1 ? s1 : (sel == 2 ? s2 : s3));
    __half* out = sel == 0 ? d0 : (sel == 1 ? d1 : (sel == 2 ? d2 : d3));
    for (int i = blockIdx.x * blockDim.x + threadIdx.x; i < n4; i += gridDim.x * blockDim.x) {
        float4 v = *(const float4*)(in + (size_t)i * 4);
        *(__half2*)(out + (size_t)i * 4)     = __floats2half2_rn(v.x, v.y);
        *(__half2*)(out + (size_t)i * 4 + 2) = __floats2half2_rn(v.z, v.w);
    }
}

__global__ void f2h2_kernel(const float* __restrict__ s0, const float* __restrict__ s1,
                            __half* __restrict__ d0, __half* __restrict__ d1, int n0, int n1)
{
    int sel = blockIdx.y;
    const float* in = sel == 0 ? s0 : s1;
    __half* out = sel == 0 ? d0 : d1;
    int n4 = sel == 0 ? n0 : n1;
    for (int i = blockIdx.x * blockDim.x + threadIdx.x; i < n4; i += gridDim.x * blockDim.x) {
        float4 v = *(const float4*)(in + (size_t)i * 4);
        *(__half2*)(out + (size_t)i * 4)     = __floats2half2_rn(v.x, v.y);
        *(__half2*)(out + (size_t)i * 4 + 2) = __floats2half2_rn(v.z, v.w);
    }
}

// ---------------- embed + posenc + LN (warp per row, fp32 out) ----------------
__global__ void embed_ln_kernel(const int* __restrict__ src, const float* __restrict__ emb,
                                const float* __restrict__ g, const float* __restrict__ bpar,
                                float* __restrict__ x)
{
    int warp = threadIdx.x >> 5, lane = threadIdx.x & 31;
    int r = blockIdx.x * 8 + warp;
    int s = r % cS;
    int tok = src[r];
    const float kPos = -9.210340371976184f / (float)cE;
    float vals[16];
    float sum = 0.f;
    const float* erow = emb + (size_t)tok * cE;
#pragma unroll
    for (int i = 0; i < 4; i++) {
        int e0 = i * 128 + lane * 4;
        float4 ev = *(const float4*)&erow[e0];
        float vv[4] = {ev.x, ev.y, ev.z, ev.w};
#pragma unroll
        for (int j = 0; j < 4; j++) {
            int e = e0 + j;
            float div = expf((float)(e & ~1) * kPos);
            float ang = (float)s * div;
            float pe = (e & 1) ? cosf(ang) : sinf(ang);
            vals[i * 4 + j] = vv[j] + pe;
            sum += vals[i * 4 + j];
        }
    }
    float mu = warp_sum(sum) * (1.f / cE);
    float vs = 0.f;
#pragma unroll
    for (int i = 0; i < 16; i++) { float d = vals[i] - mu; vs += d * d; }
    float rstd = rsqrtf(warp_sum(vs) * (1.f / cE) + 1e-5f);
    float* xrow = x + (size_t)r * cE;
#pragma unroll
    for (int i = 0; i < 4; i++) {
        int e0 = i * 128 + lane * 4;
        float4 gv = *(const float4*)&g[e0];
        float4 bv = *(const float4*)&bpar[e0];
        float4 ov;
        ov.x = (vals[i * 4 + 0] - mu) * rstd * gv.x + bv.x;
        ov.y = (vals[i * 4 + 1] - mu) * rstd * gv.y + bv.y;
        ov.z = (vals[i * 4 + 2] - mu) * rstd * gv.z + bv.z;
        ov.w = (vals[i * 4 + 3] - mu) * rstd * gv.w + bv.w;
        *(float4*)&xrow[e0] = ov;
    }
}

// LN producing fp16 (warp per row); optionally initializes gmax
__global__ void ln_kernel_h(const float* __restrict__ in, const float* __restrict__ g,
                            const float* __restrict__ bpar, __half* __restrict__ out,
                            float* gmax_init)
{
    int warp = threadIdx.x >> 5, lane = threadIdx.x & 31;
    int r = blockIdx.x * 8 + warp;
    if (gmax_init && r == 0 && lane == 0) *gmax_init = -3.4e38f;
    const float* row = in + (size_t)r * cE;
    float vals[16];
    float sum = 0.f;
#pragma unroll
    for (int i = 0; i < 4; i++) {
        float4 v = *(const float4*)&row[i * 128 + lane * 4];
        vals[i * 4 + 0] = v.x; vals[i * 4 + 1] = v.y;
        vals[i * 4 + 2] = v.z; vals[i * 4 + 3] = v.w;
        sum += v.x + v.y + v.z + v.w;
    }
    float mu = warp_sum(sum) * (1.f / cE);
    float vs = 0.f;
#pragma unroll
    for (int i = 0; i < 16; i++) { float d = vals[i] - mu; vs += d * d; }
    float rstd = rsqrtf(warp_sum(vs) * (1.f / cE) + 1e-5f);
    __half* orow = out + (size_t)r * cE;
#pragma unroll
    for (int i = 0; i < 4; i++) {
        int e0 = i * 128 + lane * 4;
        float4 gv = *(const float4*)&g[e0];
        float4 bv = *(const float4*)&bpar[e0];
        float o0 = (vals[i * 4 + 0] - mu) * rstd * gv.x + bv.x;
        float o1 = (vals[i * 4 + 1] - mu) * rstd * gv.y + bv.y;
        float o2 = (vals[i * 4 + 2] - mu) * rstd * gv.z + bv.z;
        float o3 = (vals[i * 4 + 3] - mu) * rstd * gv.w + bv.w;
        *(__half2*)&orow[e0]     = __floats2half2_rn(o0, o1);
        *(__half2*)&orow[e0 + 2] = __floats2half2_rn(o2, o3);
    }
}

// ---------------- FP16 tensor-core GEMM: 4-stage cp.async + ldmatrix (128x128) ----------------
constexpr int AST2 = 24;
constexpr int BST2 = 136;
constexpr int HSTG = 4;
constexpr int ASZ = 128 * AST2;
constexpr int BSZ = 16 * BST2;
constexpr size_t GEMM_SMEM_BYTES = (size_t)HSTG * (ASZ + BSZ) * 2;

__global__ __launch_bounds__(256, 2)
void gemm_f16(const __half* __restrict__ A, const __half* __restrict__ Bm,
              const float* __restrict__ bias, const float* __restrict__ res,
              float* __restrict__ C, __half* __restrict__ Ch, int N, int K, int act)
{
    extern __shared__ __half hsm[];
    __half* Asm = hsm;
    __half* Bsm = hsm + (size_t)HSTG * ASZ;

    int tid = threadIdx.x;
    int warp = tid >> 5, lane = tid & 31;
    int wm = warp >> 2, wn = warp & 3;
    int g = lane >> 2, t4 = lane & 3;
    int row0 = blockIdx.y * 128, col0 = blockIdx.x * 128;

    int arow = tid >> 1, ac8 = (tid & 1) * 8;
    int brow = tid >> 4, bc8 = (tid & 15) * 8;

    const __half* Ap = A + (size_t)(row0 + arow) * K + ac8;
    const __half* Bp = Bm + (size_t)brow * N + col0 + bc8;
    unsigned aBase = (unsigned)__cvta_generic_to_shared(Asm) + (unsigned)(arow * AST2 + ac8) * 2;
    unsigned bBase = (unsigned)__cvta_generic_to_shared(Bsm) + (unsigned)(brow * BST2 + bc8) * 2;
    unsigned aLds = (unsigned)__cvta_generic_to_shared(Asm);
    unsigned bLds = (unsigned)__cvta_generic_to_shared(Bsm);

    int nT = K >> 4;

    auto issue = [&](int t) {
        int s = t & (HSTG - 1);
        cp16(aBase + (unsigned)s * (ASZ * 2), Ap + (size_t)t * 16);
        cp16(bBase + (unsigned)s * (BSZ * 2), Bp + (size_t)(t * 16) * N);
    };

    float acc[4][4][4];
#pragma unroll
    for (int mi = 0; mi < 4; mi++)
#pragma unroll
        for (int ni = 0; ni < 4; ni++)
#pragma unroll
            for (int q = 0; q < 4; q++) acc[mi][ni][q] = 0.f;

    issue(0); cp_commit();
    issue(1); cp_commit();
    issue(2); cp_commit();

    int aRowSel = lane & 15;
    int aColSel = (lane >> 4) * 8;
    int bRowSel = lane & 15;

    for (int t = 0; t < nT; t++) {
        cp_wait<2>();
        __syncthreads();
        if (t + 3 < nT) issue(t + 3);
        cp_commit();
        int s = t & (HSTG - 1);
        unsigned aS = aLds + (unsigned)s * (ASZ * 2);
        unsigned bS = bLds + (unsigned)s * (BSZ * 2);

        unsigned afr[4][4];
#pragma unroll
        for (int mi = 0; mi < 4; mi++) {
            int row = wm * 64 + mi * 16 + aRowSel;
            ldsm_x4(afr[mi][0], afr[mi][1], afr[mi][2], afr[mi][3],
                    aS + (unsigned)(row * AST2 + aColSel) * 2);
        }
        unsigned bfr[4][2];
#pragma unroll
        for (int ni = 0; ni < 4; ni++) {
            int n = wn * 32 + ni * 8;
            ldsm_x2t(bfr[ni][0], bfr[ni][1], bS + (unsigned)(bRowSel * BST2 + n) * 2);
        }
#pragma unroll
        for (int ni = 0; ni < 4; ni++)
#pragma unroll
            for (int mi = 0; mi < 4; mi++)
                mma_f16(acc[mi][ni], afr[mi], bfr[ni][0], bfr[ni][1]);
    }

#pragma unroll
    for (int mi = 0; mi < 4; mi++) {
#pragma unroll
        for (int ni = 0; ni < 4; ni++) {
            int row = row0 + wm * 64 + mi * 16 + g;
            int col = col0 + wn * 32 + ni * 8 + 2 * t4;
#pragma unroll
            for (int half_ = 0; half_ < 2; half_++) {
                int r = row + half_ * 8;
                float v0 = acc[mi][ni][half_ * 2 + 0];
                float v1 = acc[mi][ni][half_ * 2 + 1];
                if (bias) { v0 += bias[col]; v1 += bias[col + 1]; }
                if (act) {
                    v0 = 0.5f * v0 * (1.f + erff(v0 * 0.70710678118654752f));
                    v1 = 0.5f * v1 * (1.f + erff(v1 * 0.70710678118654752f));
                }
                if (res) {
                    v0 += res[(size_t)r * N + col];
                    v1 += res[(size_t)r * N + col + 1];
                }
                if (C)  *(float2*)&C[(size_t)r * N + col] = make_float2(v0, v1);
                if (Ch) *(__half2*)&Ch[(size_t)r * N + col] = __floats2half2_rn(v0, v1);
            }
        }
    }
}

// fused QKV (128-row tiles): grid.x in [0,12): sel = bx/4; all outputs fp16
__global__ __launch_bounds__(256, 2)
void gemm_qkv(const __half* __restrict__ A, const __half* __restrict__ Bq,
              const __half* __restrict__ Bk, const __half* __restrict__ Bv,
              __half* __restrict__ Cq, __half* __restrict__ Ck, __half* __restrict__ Cv)
{
    constexpr int N = cE, K = cE;
    extern __shared__ __half hsm[];
    __half* Asm = hsm;
    __half* Bsm = hsm + (size_t)HSTG * ASZ;

    int tid = threadIdx.x;
    int warp = tid >> 5, lane = tid & 31;
    int wm = warp >> 2, wn = warp & 3;
    int g = lane >> 2, t4 = lane & 3;
    int bx = blockIdx.x;
    int sel = bx >> 2;
    const __half* Bm = sel == 0 ? Bq : (sel == 1 ? Bk : Bv);
    __half* C = sel == 0 ? Cq : (sel == 1 ? Ck : Cv);
    int row0 = blockIdx.y * 128, col0 = (bx & 3) * 128;

    int arow = tid >> 1, ac8 = (tid & 1) * 8;
    int brow = tid >> 4, bc8 = (tid & 15) * 8;

    const __half* Ap = A + (size_t)(row0 + arow) * K + ac8;
    const __half* Bp = Bm + (size_t)brow * N + col0 + bc8;
    unsigned aBase = (unsigned)__cvta_generic_to_shared(Asm) + (unsigned)(arow * AST2 + ac8) * 2;
    unsigned bBase = (unsigned)__cvta_generic_to_shared(Bsm) + (unsigned)(brow * BST2 + bc8) * 2;
    unsigned aLds = (unsigned)__cvta_generic_to_shared(Asm);
    unsigned bLds = (unsigned)__cvta_generic_to_shared(Bsm);

    int nT = K >> 4;

    auto issue = [&](int t) {
        int s = t & (HSTG - 1);
        cp16(aBase + (unsigned)s * (ASZ * 2), Ap + (size_t)t * 16);
        cp16(bBase + (unsigned)s * (BSZ * 2), Bp + (size_t)(t * 16) * N);
    };

    float acc[4][4][4];
#pragma unroll
    for (int mi = 0; mi < 4; mi++)
#pragma unroll
        for (int ni = 0; ni < 4; ni++)
#pragma unroll
            for (int q = 0; q < 4; q++) acc[mi][ni][q] = 0.f;

    issue(0); cp_commit();
    issue(1); cp_commit();
    issue(2); cp_commit();

    int aRowSel = lane & 15;
    int aColSel = (lane >> 4) * 8;
    int bRowSel = lane & 15;

    for (int t = 0; t < nT; t++) {
        cp_wait<2>();
        __syncthreads();
        if (t + 3 < nT) issue(t + 3);
        cp_commit();
        int s = t & (HSTG - 1);
        unsigned aS = aLds + (unsigned)s * (ASZ * 2);
        unsigned bS = bLds + (unsigned)s * (BSZ * 2);

        unsigned afr[4][4];
#pragma unroll
        for (int mi = 0; mi < 4; mi++) {
            int row = wm * 64 + mi * 16 + aRowSel;
            ldsm_x4(afr[mi][0], afr[mi][1], afr[mi][2], afr[mi][3],
                    aS + (unsigned)(row * AST2 + aColSel) * 2);
        }
        unsigned bfr[4][2];
#pragma unroll
        for (int ni = 0; ni < 4; ni++) {
            int n = wn * 32 + ni * 8;
            ldsm_x2t(bfr[ni][0], bfr[ni][1], bS + (unsigned)(bRowSel * BST2 + n) * 2);
        }
#pragma unroll
        for (int ni = 0; ni < 4; ni++)
#pragma unroll
            for (int mi = 0; mi < 4; mi++)
                mma_f16(acc[mi][ni], afr[mi], bfr[ni][0], bfr[ni][1]);
    }

#pragma unroll
    for (int mi = 0; mi < 4; mi++) {
#pragma unroll
        for (int ni = 0; ni < 4; ni++) {
            int row = row0 + wm * 64 + mi * 16 + g;
            int col = col0 + wn * 32 + ni * 8 + 2 * t4;
#pragma unroll
            for (int half_ = 0; half_ < 2; half_++) {
                int r = row + half_ * 8;
                *(__half2*)&C[(size_t)r * N + col] =
                    __floats2half2_rn(acc[mi][ni][half_ * 2 + 0], acc[mi][ni][half_ * 2 + 1]);
            }
        }
    }
}

// ---------------- MMA FAVOR+ features: xd = x @ proj^T ----------------
constexpr int XST = 72;
constexpr size_t FEATM_BYTES = (size_t)(128 + 128 + 256) * XST * 2 + (128 * 2 + 8) * 4;

__global__ void feat_qk_mma(const __half* __restrict__ qH, const __half* __restrict__ kH,
                            const __half* __restrict__ projH, __half* __restrict__ qfh,
                            __half* __restrict__ kfh, float* __restrict__ kdiag,
                            float* __restrict__ gmax)
{
    extern __shared__ __half fh[];
    __half* xq = fh;                       // [128][72]
    __half* xk = xq + 128 * XST;           // [128][72]
    __half* pj = xk + 128 * XST;           // [256][72]
    float* ssqq = (float*)(pj + 256 * XST);  // [128]
    float* ssqk = ssqq + 128;                // [128]
    float* wmax = ssqk + 128;                // [8]

    int s0 = blockIdx.x * 128;
    int bh = blockIdx.y;
    int b = bh / cH, h = bh % cH;
    int tid = threadIdx.x, warp = tid >> 5, lane = tid & 31;

    for (int i = tid; i < 128 * 8; i += 256) {
        int r = i >> 3, c = (i & 7) * 8;
        size_t gi = (size_t)(b * cS + s0 + r) * cE + h * cDH + c;
        *(uint4*)&xq[r * XST + c] = *(const uint4*)&qH[gi];
        *(uint4*)&xk[r * XST + c] = *(const uint4*)&kH[gi];
    }
    for (int i = tid; i < 256 * 8; i += 256) {
        int r = i >> 3, c = (i & 7) * 8;
        *(uint4*)&pj[r * XST + c] = *(const uint4*)&projH[(size_t)r * cDH + c];
    }
    __syncthreads();
    {
        int r = tid & 127;
        const __half* xp = (tid < 128) ? &xq[r * XST] : &xk[r * XST];
        float acc = 0.f;
#pragma unroll
        for (int d = 0; d < 64; d += 2) {
            float2 f = __half22float2(*(const __half2*)&xp[d]);
            acc += f.x * f.x + f.y * f.y;
        }
        if (tid < 128) ssqq[r] = acc; else ssqk[r] = acc;
    }
    __syncthreads();

    unsigned xqb = (unsigned)__cvta_generic_to_shared(xq);
    unsigned xkb = (unsigned)__cvta_generic_to_shared(xk);
    unsigned pjb = (unsigned)__cvta_generic_to_shared(pj);

    int l16 = lane & 15, lhi = lane >> 4;
    int lq = lane & 7, grp = lane >> 3;
    int g = lane >> 2, t4 = lane & 3;
    int m0 = warp * 16;
    const float dn = 0.35355339059327373f;
    const float dn2 = 0.5f * dn * dn;

    int rowlo = m0 + g, rowhi = rowlo + 8;
    size_t orow_lo = ((size_t)bh * cS + s0 + rowlo) * cM;
    size_t orow_hi = ((size_t)bh * cS + s0 + rowhi) * cM;

    // ---- q phase ----
    {
        float acc[32][4];
#pragma unroll
        for (int j = 0; j < 32; j++)
#pragma unroll
            for (int q = 0; q < 4; q++) acc[j][q] = 0.f;

#pragma unroll
        for (int ks = 0; ks < 4; ks++) {
            int k0 = ks * 16;
            unsigned a4[4];
            ldsm_x4(a4[0], a4[1], a4[2], a4[3],
                    xqb + (unsigned)((m0 + l16) * XST + k0 + 8 * lhi) * 2);
#pragma unroll
            for (int nf = 0; nf < 16; nf++) {
                unsigned b4[4];
                int nrow = nf * 16 + lq + ((grp & 2) ? 8 : 0);
                int kcol = k0 + ((grp & 1) ? 8 : 0);
                ldsm_x4(b4[0], b4[1], b4[2], b4[3], pjb + (unsigned)(nrow * XST + kcol) * 2);
                mma_f16(acc[2 * nf],     a4, b4[0], b4[1]);
                mma_f16(acc[2 * nf + 1], a4, b4[2], b4[3]);
            }
        }
        float mlo = acc[0][0], mhi = acc[0][2];
#pragma unroll
        for (int j = 0; j < 32; j++) {
            mlo = fmaxf(mlo, fmaxf(acc[j][0], acc[j][1]));
            mhi = fmaxf(mhi, fmaxf(acc[j][2], acc[j][3]));
        }
#pragma unroll
        for (int s = 1; s < 4; s <<= 1) {
            mlo = fmaxf(mlo, __shfl_xor_sync(0xffffffff, mlo, s));
            mhi = fmaxf(mhi, __shfl_xor_sync(0xffffffff, mhi, s));
        }
        float elo = ssqq[rowlo] * dn2 + mlo * dn;
        float ehi = ssqq[rowhi] * dn2 + mhi * dn;
#pragma unroll
        for (int j = 0; j < 32; j++) {
            int col = j * 8 + 2 * t4;
            float v0 = 0.0625f * (__expf(acc[j][0] * dn - elo) + 1e-4f);
            float v1 = 0.0625f * (__expf(acc[j][1] * dn - elo) + 1e-4f);
            float v2 = 0.0625f * (__expf(acc[j][2] * dn - ehi) + 1e-4f);
            float v3 = 0.0625f * (__expf(acc[j][3] * dn - ehi) + 1e-4f);
            *(__half2*)&qfh[orow_lo + col] = __floats2half2_rn(v0, v1);
            *(__half2*)&qfh[orow_hi + col] = __floats2half2_rn(v2, v3);
        }
    }

    // ---- k phase ----
    {
        float acc[32][4];
#pragma unroll
        for (int j = 0; j < 32; j++)
#pragma unroll
            for (int q = 0; q < 4; q++) acc[j][q] = 0.f;

#pragma unroll
        for (int ks = 0; ks < 4; ks++) {
            int k0 = ks * 16;
            unsigned a4[4];
            ldsm_x4(a4[0], a4[1], a4[2], a4[3],
                    xkb + (unsigned)((m0 + l16) * XST + k0 + 8 * lhi) * 2);
#pragma unroll
            for (int nf = 0; nf < 16; nf++) {
                unsigned b4[4];
                int nrow = nf * 16 + lq + ((grp & 2) ? 8 : 0);
                int kcol = k0 + ((grp & 1) ? 8 : 0);
                ldsm_x4(b4[0], b4[1], b4[2], b4[3], pjb + (unsigned)(nrow * XST + kcol) * 2);
                mma_f16(acc[2 * nf],     a4, b4[0], b4[1]);
                mma_f16(acc[2 * nf + 1], a4, b4[2], b4[3]);
            }
        }
        float tm = acc[0][0];
#pragma unroll
        for (int j = 0; j < 32; j++) {
            int col = j * 8 + 2 * t4;
            float v0 = acc[j][0] * dn, v1 = acc[j][1] * dn;
            float v2 = acc[j][2] * dn, v3 = acc[j][3] * dn;
            *(__half2*)&kfh[orow_lo + col] = __floats2half2_rn(v0, v1);
            *(__half2*)&kfh[orow_hi + col] = __floats2half2_rn(v2, v3);
            tm = fmaxf(tm, fmaxf(fmaxf(acc[j][0], acc[j][1]), fmaxf(acc[j][2], acc[j][3])));
        }
#pragma unroll
        for (int s = 16; s > 0; s >>= 1) tm = fmaxf(tm, __shfl_xor_sync(0xffffffff, tm, s));
        if (lane == 0) wmax[warp] = tm * dn;
    }
    if (tid < 128) kdiag[(size_t)bh * cS + s0 + tid] = ssqk[tid] * dn2;
    __syncthreads();
    if (tid == 0) {
        float mx = wmax[0];
#pragma unroll
        for (int w = 1; w < 8; w++) mx = fmaxf(mx, wmax[w]);
        atomicMaxFloat(gmax, mx);
    }
}

// ---------------- attention phase A: MMA chunk sums with fused exp ----------------
constexpr int CKST = 264;
constexpr int CVST = 88;
constexpr size_t CHUNK_SMEM_BYTES = (size_t)(128 * CKST + 128 * CVST) * 2 + 128 * 4;

__global__ void attn_chunk_mma(const float* __restrict__ kdiag, const float* __restrict__ gmax,
                               const __half* __restrict__ vH, __half* __restrict__ kfh,
                               float* __restrict__ kvsum, float* __restrict__ zc)
{
    extern __shared__ __half csm[];
    __half* kfs = csm;
    __half* vsm = kfs + 128 * CKST;
    float* kdsh = (float*)(vsm + 128 * CVST);

    int ch = blockIdx.x, bh = blockIdx.y;
    int b = bh / cH, h = bh % cH;
    int tid = threadIdx.x, warp = tid >> 5, lane = tid & 31;
    int c0 = ch * cCHUNK;

    __half* kg = kfh + ((size_t)bh * cS + c0) * cM;
    for (int i = tid; i < 128 * 32; i += 256) {
        int r = i >> 5, c = (i & 31) * 8;
        *(uint4*)&kfs[r * CKST + c] = *(const uint4*)&kg[(size_t)r * cM + c];
    }
    const __half* vg = vH + (size_t)(b * cS + c0) * cE + h * cDH;
    for (int i = tid; i < 128 * 8; i += 256) {
        int r = i >> 3, c = (i & 7) * 8;
        *(uint4*)&vsm[r * CVST + c] = *(const uint4*)&vg[(size_t)r * cE + c];
    }
    for (int i = tid; i < 128 * 16; i += 256) {
        int r = i >> 4, c = 64 + (i & 15);
        vsm[r * CVST + c] = (c == 64) ? __float2half(1.f) : __float2half(0.f);
    }
    if (tid < 128) kdsh[tid] = kdiag[(size_t)bh * cS + c0 + tid];
    float gm = *gmax;
    __syncthreads();

    for (int i = tid; i < 128 * 256; i += 256) {
        int s = i >> 8, m = i & 255;
        float raw = __half2float(kfs[s * CKST + m]);
        float kv = 0.0625f * (__expf(raw - kdsh[s] - gm) + 1e-4f);
        __half hv = __float2half(kv);
        kfs[s * CKST + m] = hv;
        kg[(size_t)s * cM + m] = hv;
    }
    __syncthreads();

    unsigned kfb = (unsigned)__cvta_generic_to_shared(kfs);
    unsigned vbb = (unsigned)__cvta_generic_to_shared(vsm);
    int lq = lane & 7, grp = lane >> 3;
    int g = lane >> 2, t4 = lane & 3;
    int m0 = warp * 32;

    float acc[2][9][4];
#pragma unroll
    for (int mi = 0; mi < 2; mi++)
#pragma unroll
        for (int j = 0; j < 9; j++)
#pragma unroll
            for (int q = 0; q < 4; q++) acc[mi][j][q] = 0.f;

#pragma unroll
    for (int ks = 0; ks < 8; ks++) {
        int k0 = ks * 16;
        int krow = k0 + lq + ((grp & 1) ? 8 : 0);
        unsigned afr[2][4];
#pragma unroll
        for (int mi = 0; mi < 2; mi++) {
            int mcol = m0 + mi * 16 + ((grp & 2) ? 8 : 0);
            unsigned t0, t1, t2, t3;
            ldsm_x4t(t0, t1, t2, t3, kfb + (unsigned)(krow * CKST + mcol) * 2);
            afr[mi][0] = t0; afr[mi][1] = t2; afr[mi][2] = t1; afr[mi][3] = t3;
        }
        unsigned bf[5][4];
#pragma unroll
        for (int nf = 0; nf < 5; nf++) {
            int ncol = nf * 16 + ((grp & 2) ? 8 : 0);
            ldsm_x4t(bf[nf][0], bf[nf][1], bf[nf][2], bf[nf][3],
                     vbb + (unsigned)(krow * CVST + ncol) * 2);
        }
#pragma unroll
        for (int j = 0; j < 9; j++) {
            int nf = j >> 1, p = j & 1;
            mma_f16(acc[0][j], afr[0], bf[nf][p * 2], bf[nf][p * 2 + 1]);
            mma_f16(acc[1][j], afr[1], bf[nf][p * 2], bf[nf][p * 2 + 1]);
        }
    }

#pragma unroll
    for (int mi = 0; mi < 2; mi++) {
        int rlo = m0 + mi * 16 + g, rhi = rlo + 8;
        float* klo = kvsum + (((size_t)bh * cNC + ch) * cM + rlo) * cDH;
        float* khi = kvsum + (((size_t)bh * cNC + ch) * cM + rhi) * cDH;
#pragma unroll
        for (int nf = 0; nf < 8; nf++) {
            int col = nf * 8 + 2 * t4;
            *(float2*)&klo[col] = make_float2(acc[mi][nf][0], acc[mi][nf][1]);
            *(float2*)&khi[col] = make_float2(acc[mi][nf][2], acc[mi][nf][3]);
        }
        if (t4 == 0) {
            zc[((size_t)bh * cNC + ch) * cM + rlo] = acc[mi][8][0];
            zc[((size_t)bh * cNC + ch) * cM + rhi] = acc[mi][8][2];
        }
    }
}

// ---------------- attention phase B: exclusive prefix -> fp16 [Sp|z] (16-way d split) ----------------
__global__ void attn_prefix(const float* __restrict__ kvsum, const float* __restrict__ zc,
                            __half* __restrict__ sphg)
{
    int bh = blockIdx.x, ds = blockIdx.y;
    int m = threadIdx.x;
    int d0 = ds * 4;
    float carry[4] = {0.f, 0.f, 0.f, 0.f};
    float zcarry = 0.f;
    for (int c = 0; c < cNC; c++) {
        const float* p = kvsum + (((size_t)bh * cNC + c) * cM + m) * cDH + d0;
        __half* sp = sphg + (((size_t)bh * cNC + c) * cM + m) * 72 + d0;
        float4 t = *(const float4*)p;
        *(__half2*)&sp[0] = __floats2half2_rn(carry[0], carry[1]);
        *(__half2*)&sp[2] = __floats2half2_rn(carry[2], carry[3]);
        carry[0] += t.x; carry[1] += t.y; carry[2] += t.z; carry[3] += t.w;
        if (ds == 0) {
            __half* spz = sphg + (((size_t)bh * cNC + c) * cM + m) * 72;
            spz[64] = __float2half(zcarry);
#pragma unroll
            for (int j = 65; j < 72; j++) spz[j] = __float2half(0.f);
            zcarry += zc[((size_t)bh * cNC + c) * cM + m];
        }
    }
}

// ---------------- attention phase C: fully-MMA per-chunk output ----------------
constexpr int QST = 264;
constexpr int ASH_ST = 136;
constexpr int VST = 88;
constexpr size_t ATT2_HALVES = (size_t)128 * QST * 2 + 128 * VST + 256 * VST;
constexpr size_t ATT2_BYTES = ATT2_HALVES * 2;

__global__ void attn_out(const __half* __restrict__ qfh, const __half* __restrict__ kfh,
                         const __half* __restrict__ vH, const __half* __restrict__ sphg,
                         __half* __restrict__ oH)
{
    extern __shared__ __half hsm2[];
    __half* qh  = hsm2;
    __half* kh  = qh + 128 * QST;
    __half* vh  = kh + 128 * QST;
    __half* sph = vh + 128 * VST;

    int ch = blockIdx.x, bh = blockIdx.y;
    int b = bh / cH, h = bh % cH;
    int tid = threadIdx.x, warp = tid >> 5, lane = tid & 31;
    int c0 = ch * cCHUNK;

    const __half* qg = qfh + ((size_t)bh * cS + c0) * cM;
    const __half* kg = kfh + ((size_t)bh * cS + c0) * cM;
    for (int i = tid; i < 128 * 32; i += 256) {
        int r = i >> 5, c = (i & 31) * 8;
        *(uint4*)&qh[r * QST + c] = *(const uint4*)&qg[(size_t)r * cM + c];
        *(uint4*)&kh[r * QST + c] = *(const uint4*)&kg[(size_t)r * cM + c];
    }
    const __half* vg = vH + (size_t)(b * cS + c0) * cE + h * cDH;
    for (int i = tid; i < 128 * 8; i += 256) {
        int r = i >> 3, c = (i & 7) * 8;
        *(uint4*)&vh[r * VST + c] = *(const uint4*)&vg[(size_t)r * cE + c];
    }
    for (int i = tid; i < 128 * 24; i += 256) {
        int r = i / 24, c = i % 24;
        vh[r * VST + 64 + c] = (c == 0) ? __float2half(1.f) : __float2half(0.f);
    }
    const __half* sg = sphg + ((size_t)bh * cNC + ch) * cM * 72;
    for (int i = tid; i < 256 * 9; i += 256) {
        int r = i / 9, c = (i % 9) * 8;
        *(uint4*)&sph[r * VST + c] = *(const uint4*)&sg[(size_t)r * 72 + c];
    }
    for (int i = tid; i < 256 * 16; i += 256) {
        int r = i >> 4, c = i & 15;
        sph[r * VST + 72 + c] = __float2half(0.f);
    }
    __syncthreads();

    unsigned qb = (unsigned)__cvta_generic_to_shared(qh);
    unsigned kb = (unsigned)__cvta_generic_to_shared(kh);
    unsigned vb = (unsigned)__cvta_generic_to_shared(vh);
    unsigned sb = (unsigned)__cvta_generic_to_shared(sph);

    int l16 = lane & 15, lhi = lane >> 4;
    int lq = lane & 7, grp = lane >> 3;
    int g = lane >> 2, t4 = lane & 3;

    // phase 1: A = qf @ kf^T
    {
        int wm = warp >> 2, wn = warp & 3;
        float accA[4][4][4];
#pragma unroll
        for (int mi = 0; mi < 4; mi++)
#pragma unroll
            for (int ni = 0; ni < 4; ni++)
#pragma unroll
                for (int q = 0; q < 4; q++) accA[mi][ni][q] = 0.f;

        for (int ks = 0; ks < 16; ks++) {
            int k0 = ks * 16;
            unsigned af[4][4];
#pragma unroll
            for (int mi = 0; mi < 4; mi++)
                ldsm_x4(af[mi][0], af[mi][1], af[mi][2], af[mi][3],
                        qb + (unsigned)((wm * 64 + mi * 16 + l16) * QST + k0 + 8 * lhi) * 2);
            unsigned bfA[2][4];
#pragma unroll
            for (int g16 = 0; g16 < 2; g16++) {
                int n0 = wn * 32 + g16 * 16;
                int nrow = n0 + lq + ((grp & 2) ? 8 : 0);
                int kcol = k0 + ((grp & 1) ? 8 : 0);
                ldsm_x4(bfA[g16][0], bfA[g16][1], bfA[g16][2], bfA[g16][3],
                        kb + (unsigned)(nrow * QST + kcol) * 2);
            }
#pragma unroll
            for (int ni = 0; ni < 4; ni++) {
                unsigned b0 = bfA[ni >> 1][(ni & 1) * 2];
                unsigned b1 = bfA[ni >> 1][(ni & 1) * 2 + 1];
#pragma unroll
                for (int mi = 0; mi < 4; mi++)
                    mma_f16(accA[mi][ni], af[mi], b0, b1);
            }
        }
        __syncthreads();
#pragma unroll
        for (int mi = 0; mi < 4; mi++) {
#pragma unroll
            for (int ni = 0; ni < 4; ni++) {
                int row = wm * 64 + mi * 16 + g;
                int col = wn * 32 + ni * 8 + 2 * t4;
                float a0 = (col <= row) ? accA[mi][ni][0] : 0.f;
                float a1 = (col + 1 <= row) ? accA[mi][ni][1] : 0.f;
                *(__half2*)&kh[row * ASH_ST + col] = __floats2half2_rn(a0, a1);
                int row2 = row + 8;
                float a2 = (col <= row2) ? accA[mi][ni][2] : 0.f;
                float a3 = (col + 1 <= row2) ? accA[mi][ni][3] : 0.f;
                *(__half2*)&kh[row2 * ASH_ST + col] = __floats2half2_rn(a2, a3);
            }
        }
        __syncthreads();
    }

    // phase 2: [num|den] = qf @ [Sp|z] + Ash @ [v|1]
    float accN[9][4];
#pragma unroll
    for (int j = 0; j < 9; j++)
#pragma unroll
        for (int q = 0; q < 4; q++) accN[j][q] = 0.f;

    int m0 = warp * 16;
    for (int ks = 0; ks < 16; ks++) {
        int k0 = ks * 16;
        unsigned af4[4];
        ldsm_x4(af4[0], af4[1], af4[2], af4[3],
                qb + (unsigned)((m0 + l16) * QST + k0 + 8 * lhi) * 2);
        unsigned bf[5][4];
        int krow = k0 + lq + ((grp & 1) ? 8 : 0);
#pragma unroll
        for (int nf = 0; nf < 5; nf++) {
            int ncol = nf * 16 + ((grp & 2) ? 8 : 0);
            ldsm_x4t(bf[nf][0], bf[nf][1], bf[nf][2], bf[nf][3],
                     sb + (unsigned)(krow * VST + ncol) * 2);
        }
#pragma unroll
        for (int j = 0; j < 9; j++) {
            int nf = j >> 1, p = j & 1;
            mma_f16(accN[j], af4, bf[nf][p * 2], bf[nf][p * 2 + 1]);
        }
    }
    for (int ks = 0; ks < 8; ks++) {
        int k0 = ks * 16;
        unsigned af4[4];
        ldsm_x4(af4[0], af4[1], af4[2], af4[3],
                kb + (unsigned)((m0 + l16) * ASH_ST + k0 + 8 * lhi) * 2);
        unsigned bf[5][4];
        int krow = k0 + lq + ((grp & 1) ? 8 : 0);
#pragma unroll
        for (int nf = 0; nf < 5; nf++) {
            int ncol = nf * 16 + ((grp & 2) ? 8 : 0);
            ldsm_x4t(bf[nf][0], bf[nf][1], bf[nf][2], bf[nf][3],
                     vb + (unsigned)(krow * VST + ncol) * 2);
        }
#pragma unroll
        for (int j = 0; j < 9; j++) {
            int nf = j >> 1, p = j & 1;
            mma_f16(accN[j], af4, bf[nf][p * 2], bf[nf][p * 2 + 1]);
        }
    }

    float denlo = __shfl_sync(0xffffffff, accN[8][0], lane & ~3);
    float denhi = __shfl_sync(0xffffffff, accN[8][2], lane & ~3);
    float invlo = 1.f / (denlo + 1e-6f);
    float invhi = 1.f / (denhi + 1e-6f);
    int rowlo = m0 + g, rowhi = rowlo + 8;
    __half* olo = oH + (size_t)(b * cS + c0 + rowlo) * cE + h * cDH;
    __half* ohi = oH + (size_t)(b * cS + c0 + rowhi) * cE + h * cDH;
#pragma unroll
    for (int nf = 0; nf < 8; nf++) {
        int col = nf * 8 + 2 * t4;
        *(__half2*)&olo[col] = __floats2half2_rn(accN[nf][0] * invlo, accN[nf][1] * invlo);
        *(__half2*)&ohi[col] = __floats2half2_rn(accN[nf][2] * invhi, accN[nf][3] * invhi);
    }
}

// ---------------- host orchestration ----------------
extern "C" void kernel_launch(void* const* d_in, const int* in_sizes, int n_in,
                              void* d_out, int out_size)
{
    const int*   src  = (const int*)d_in[0];
    const float* emb  = (const float*)d_in[2];
    const float* lng  = (const float*)d_in[3];
    const float* lnb  = (const float*)d_in[4];
    const float* Wq   = (const float*)d_in[5];
    const float* Wk   = (const float*)d_in[6];
    const float* Wv   = (const float*)d_in[7];
    const float* Wo   = (const float*)d_in[8];
    const float* ln1g = (const float*)d_in[9];
    const float* ln1b = (const float*)d_in[10];
    const float* W1   = (const float*)d_in[11];
    const float* b1   = (const float*)d_in[12];
    const float* W2   = (const float*)d_in[13];
    const float* b2   = (const float*)d_in[14];
    const float* ln2g = (const float*)d_in[15];
    const float* ln2b = (const float*)d_in[16];
    const float* proj = (const float*)d_in[17];
    const float* fcw  = (const float*)d_in[18];
    const float* fcb  = (const float*)d_in[19];
    float* out = (float*)d_out;

    float* sc = nullptr;
    cudaGetSymbolAddress((void**)&sc, g_scratch);
    __half* sh = nullptr;
    cudaGetSymbolAddress((void**)&sh, g_scratch_h);

    float* x    = sc + OFF_X;
    float* kd   = sc + OFF_KD;
    float* kvs  = sc + OFF_KV;
    float* zcb  = sc + OFF_ZC;
    float* gmax = sc + OFF_GMAX;

    __half* hH   = sh + HOFF_H;
    __half* oH   = sh + HOFF_O;
    __half* ffnH = sh + HOFF_FFN;
    __half* xH   = sh + HOFF_XH;
    __half* vH   = sh + HOFF_VH;
    __half* qH   = sh + HOFF_QH;
    __half* kH   = sh + HOFF_KH;
    __half* qfh  = sh + HOFF_QFH;
    __half* kfh  = sh + HOFF_KFH;
    __half* sphg = sh + HOFF_SPH;
    __half* pjH  = sh + HOFF_PJ;
    __half* WqH  = sh + HOFF_WQ;
    __half* WkH  = sh + HOFF_WK;
    __half* WvH  = sh + HOFF_WV;
    __half* WoH  = sh + HOFF_WO;
    __half* W1H  = sh + HOFF_W1;
    __half* W2H  = sh + HOFF_W2;
    __half* fcwH = sh + HOFF_FCW;

    cudaFuncSetAttribute(gemm_f16, cudaFuncAttributeMaxDynamicSharedMemorySize, (int)GEMM_SMEM_BYTES);
    cudaFuncSetAttribute(gemm_qkv, cudaFuncAttributeMaxDynamicSharedMemorySize, (int)GEMM_SMEM_BYTES);
    cudaFuncSetAttribute(attn_out, cudaFuncAttributeMaxDynamicSharedMemorySize, (int)ATT2_BYTES);
    cudaFuncSetAttribute(feat_qk_mma, cudaFuncAttributeMaxDynamicSharedMemorySize, (int)FEATM_BYTES);
    cudaFuncSetAttribute(attn_chunk_mma, cudaFuncAttributeMaxDynamicSharedMemorySize, (int)CHUNK_SMEM_BYTES);

    int nWsm = cL * cE * cE / 4;
    int nWff = cL * cE * 4 * cE / 4;
    int nFcw = cE * cV / 4;
    int nPj  = cL * cM * cDH / 4;
    f2h4_kernel<<<dim3(256, 4), 256>>>(Wq, Wk, Wv, Wo, WqH, WkH, WvH, WoH, nWsm);
    f2h4_kernel<<<dim3(512, 2), 256>>>(W1, W2, W1, W2, W1H, W2H, W1H, W2H, nWff);
    f2h2_kernel<<<dim3(1024, 2), 256>>>(fcw, proj, fcwH, pjH, nFcw, nPj);

    embed_ln_kernel<<<cBS / 8, 256>>>(src, emb, lng, lnb, x);

    dim3 g512(cE / 128, cBS / 128);
    dim3 gF1(4 * cE / 128, cBS / 128);
    dim3 gQKV(12, cBS / 128);
    dim3 gFeatM(cS / 128, cBH);
    dim3 gChunk(cNC, cBH);
    dim3 gPfx(cBH, 16);

    for (int l = 0; l < cL; l++) {
        ln_kernel_h<<<cBS / 8, 256>>>(x, ln1g + (size_t)l * cE, ln1b + (size_t)l * cE, hH, gmax);
        gemm_qkv<<<gQKV, 256, GEMM_SMEM_BYTES>>>(hH, WqH + (size_t)l * cE * cE,
                                                 WkH + (size_t)l * cE * cE,
                                                 WvH + (size_t)l * cE * cE, qH, kH, vH);

        feat_qk_mma<<<gFeatM, 256, FEATM_BYTES>>>(qH, kH, pjH + (size_t)l * cM * cDH,
                                                  qfh, kfh, kd, gmax);

        attn_chunk_mma<<<gChunk, 256, CHUNK_SMEM_BYTES>>>(kd, gmax, vH, kfh, kvs, zcb);
        attn_prefix<<<gPfx, 256>>>(kvs, zcb, sphg);
        attn_out<<<gChunk, 256, ATT2_BYTES>>>(qfh, kfh, vH, sphg, oH);

        gemm_f16<<<g512, 256, GEMM_SMEM_BYTES>>>(oH, WoH + (size_t)l * cE * cE,
                                                 nullptr, x, x, nullptr, cE, cE, 0);

        ln_kernel_h<<<cBS / 8, 256>>>(x, ln2g + (size_t)l * cE, ln2b + (size_t)l * cE, hH, nullptr);
        gemm_f16<<<gF1, 256, GEMM_SMEM_BYTES>>>(hH, W1H + (size_t)l * cE * 4 * cE,
                                                b1 + (size_t)l * 4 * cE, nullptr,
                                                nullptr, ffnH, 4 * cE, cE, 1);
        gemm_f16<<<g512, 256, GEMM_SMEM_BYTES>>>(ffnH, W2H + (size_t)l * cE * 4 * cE,
                                                 b2 + (size_t)l * cE, x, x, xH, cE, 4 * cE, 0);
    }

    gemm_f16<<<dim3(cV / 128, cBS / 128), 256, GEMM_SMEM_BYTES>>>(
        xH, fcwH, fcb, nullptr, out, nullptr, cV, cE, 0);
}

// round 17
// speedup vs baseline: 1.5071x; 1.5071x over previous
#include <cuda_runtime.h>
#include <cuda_bf16.h>
#include <cuda_fp16.h>
#include <math.h>
#include <stdint.h>

constexpr int cB = 2, cS = 2048, cV = 32000, cE = 512, cH = 8, cL = 4;
constexpr int cDH = 64, cM = 256, cCHUNK = 128;
constexpr int cBS = cB * cS;
constexpr int cBH = cB * cH;
constexpr int cNC = cS / cCHUNK;

constexpr size_t OFF_X    = 0;
constexpr size_t OFF_KD   = OFF_X + (size_t)cBS * cE;
constexpr size_t OFF_KV   = OFF_KD + (size_t)cBH * cS;
constexpr size_t OFF_ZC   = OFF_KV + (size_t)cBH * cNC * cM * cDH;
constexpr size_t OFF_GMAX = OFF_ZC + (size_t)cBH * cNC * cM;
constexpr size_t SCRATCH_FLOATS = OFF_GMAX + 64;

__device__ float g_scratch[SCRATCH_FLOATS];

constexpr size_t HOFF_H   = 0;
constexpr size_t HOFF_O   = HOFF_H + (size_t)cBS * cE;
constexpr size_t HOFF_FFN = HOFF_O + (size_t)cBS * cE;
constexpr size_t HOFF_XH  = HOFF_FFN + (size_t)cBS * 4 * cE;
constexpr size_t HOFF_VH  = HOFF_XH + (size_t)cBS * cE;
constexpr size_t HOFF_QH  = HOFF_VH + (size_t)cBS * cE;
constexpr size_t HOFF_KH  = HOFF_QH + (size_t)cBS * cE;
constexpr size_t HOFF_QFH = HOFF_KH + (size_t)cBS * cE;
constexpr size_t HOFF_KFH = HOFF_QFH + (size_t)cBH * cS * cM;
constexpr size_t HOFF_SPH = HOFF_KFH + (size_t)cBH * cS * cM;
constexpr size_t HOFF_PJ  = HOFF_SPH + (size_t)cBH * cNC * cM * 72;
constexpr size_t HOFF_WQ  = HOFF_PJ + (size_t)cL * cM * cDH;
constexpr size_t HOFF_WK  = HOFF_WQ + (size_t)cL * cE * cE;
constexpr size_t HOFF_WV  = HOFF_WK + (size_t)cL * cE * cE;
constexpr size_t HOFF_WO  = HOFF_WV + (size_t)cL * cE * cE;
constexpr size_t HOFF_W1  = HOFF_WO + (size_t)cL * cE * cE;
constexpr size_t HOFF_W2  = HOFF_W1 + (size_t)cL * cE * 4 * cE;
constexpr size_t HOFF_FCW = HOFF_W2 + (size_t)cL * cE * 4 * cE;
constexpr size_t SCRATCH_HALVES = HOFF_FCW + (size_t)cE * cV;

__device__ __half g_scratch_h[SCRATCH_HALVES];

__device__ __forceinline__ void atomicMaxFloat(float* addr, float value) {
    if (value >= 0.f) atomicMax((int*)addr, __float_as_int(value));
    else              atomicMin((unsigned int*)addr, __float_as_uint(value));
}

__device__ __forceinline__ void mma_f16(float* c, const unsigned* a, unsigned b0, unsigned b1) {
    asm volatile("mma.sync.aligned.m16n8k16.row.col.f32.f16.f16.f32 "
        "{%0,%1,%2,%3}, {%4,%5,%6,%7}, {%8,%9}, {%0,%1,%2,%3};"
        : "+f"(c[0]), "+f"(c[1]), "+f"(c[2]), "+f"(c[3])
        : "r"(a[0]), "r"(a[1]), "r"(a[2]), "r"(a[3]), "r"(b0), "r"(b1));
}

__device__ __forceinline__ void ldsm_x4(unsigned& r0, unsigned& r1, unsigned& r2, unsigned& r3,
                                        unsigned addr) {
    asm volatile("ldmatrix.sync.aligned.m8n8.x4.shared.b16 {%0,%1,%2,%3}, [%4];"
        : "=r"(r0), "=r"(r1), "=r"(r2), "=r"(r3) : "r"(addr));
}
__device__ __forceinline__ void ldsm_x4t(unsigned& r0, unsigned& r1, unsigned& r2, unsigned& r3,
                                         unsigned addr) {
    asm volatile("ldmatrix.sync.aligned.m8n8.x4.trans.shared.b16 {%0,%1,%2,%3}, [%4];"
        : "=r"(r0), "=r"(r1), "=r"(r2), "=r"(r3) : "r"(addr));
}
__device__ __forceinline__ void ldsm_x2t(unsigned& r0, unsigned& r1, unsigned addr) {
    asm volatile("ldmatrix.sync.aligned.m8n8.x2.trans.shared.b16 {%0,%1}, [%2];"
        : "=r"(r0), "=r"(r1) : "r"(addr));
}

__device__ __forceinline__ void cp16(unsigned dst, const void* src) {
    asm volatile("cp.async.cg.shared.global [%0], [%1], 16;" :: "r"(dst), "l"(src));
}
__device__ __forceinline__ void cp_commit() { asm volatile("cp.async.commit_group;"); }
template<int n> __device__ __forceinline__ void cp_wait() {
    asm volatile("cp.async.wait_group %0;" :: "n"(n));
}

__device__ __forceinline__ float warp_sum(float v) {
#pragma unroll
    for (int s = 16; s > 0; s >>= 1) v += __shfl_xor_sync(0xffffffff, v, s);
    return v;
}

__global__ void f2h4_kernel(const float* __restrict__ s0, const float* __restrict__ s1,
                            const float* __restrict__ s2, const float* __restrict__ s3,
                            __half* __restrict__ d0, __half* __restrict__ d1,
                            __half* __restrict__ d2, __half* __restrict__ d3, int n4)
{
    int sel = blockIdx.y;
    const float* in = sel == 0 ? s0 : (sel == 1 ? s1 : (sel == 2 ? s2 : s3));
    __half* out = sel == 0 ? d0 : (sel == 1 ? d1 : (sel == 2 ? d2 : d3));
    for (int i = blockIdx.x * blockDim.x + threadIdx.x; i < n4; i += gridDim.x * blockDim.x) {
        float4 v = *(const float4*)(in + (size_t)i * 4);
        *(__half2*)(out + (size_t)i * 4)     = __floats2half2_rn(v.x, v.y);
        *(__half2*)(out + (size_t)i * 4 + 2) = __floats2half2_rn(v.z, v.w);
    }
}

__global__ void f2h2_kernel(const float* __restrict__ s0, const float* __restrict__ s1,
                            __half* __restrict__ d0, __half* __restrict__ d1, int n0, int n1)
{
    int sel = blockIdx.y;
    const float* in = sel == 0 ? s0 : s1;
    __half* out = sel == 0 ? d0 : d1;
    int n4 = sel == 0 ? n0 : n1;
    for (int i = blockIdx.x * blockDim.x + threadIdx.x; i < n4; i += gridDim.x * blockDim.x) {
        float4 v = *(const float4*)(in + (size_t)i * 4);
        *(__half2*)(out + (size_t)i * 4)     = __floats2half2_rn(v.x, v.y);
        *(__half2*)(out + (size_t)i * 4 + 2) = __floats2half2_rn(v.z, v.w);
    }
}

__global__ void embed_ln_kernel(const int* __restrict__ src, const float* __restrict__ emb,
                                const float* __restrict__ g, const float* __restrict__ bpar,
                                float* __restrict__ x)
{
    int warp = threadIdx.x >> 5, lane = threadIdx.x & 31;
    int r = blockIdx.x * 8 + warp;
    int s = r % cS;
    int tok = src[r];
    const float kPos = -9.210340371976184f / (float)cE;
    float vals[16];
    float sum = 0.f;
    const float* erow = emb + (size_t)tok * cE;
#pragma unroll
    for (int i = 0; i < 4; i++) {
        int e0 = i * 128 + lane * 4;
        float4 ev = *(const float4*)&erow[e0];
        float vv[4] = {ev.x, ev.y, ev.z, ev.w};
#pragma unroll
        for (int j = 0; j < 4; j++) {
            int e = e0 + j;
            float div = expf((float)(e & ~1) * kPos);
            float ang = (float)s * div;
            float pe = (e & 1) ? cosf(ang) : sinf(ang);
            vals[i * 4 + j] = vv[j] + pe;
            sum += vals[i * 4 + j];
        }
    }
    float mu = warp_sum(sum) * (1.f / cE);
    float vs = 0.f;
#pragma unroll
    for (int i = 0; i < 16; i++) { float d = vals[i] - mu; vs += d * d; }
    float rstd = rsqrtf(warp_sum(vs) * (1.f / cE) + 1e-5f);
    float* xrow = x + (size_t)r * cE;
#pragma unroll
    for (int i = 0; i < 4; i++) {
        int e0 = i * 128 + lane * 4;
        float4 gv = *(const float4*)&g[e0];
        float4 bv = *(const float4*)&bpar[e0];
        float4 ov;
        ov.x = (vals[i * 4 + 0] - mu) * rstd * gv.x + bv.x;
        ov.y = (vals[i * 4 + 1] - mu) * rstd * gv.y + bv.y;
        ov.z = (vals[i * 4 + 2] - mu) * rstd * gv.z + bv.z;
        ov.w = (vals[i * 4 + 3] - mu) * rstd * gv.w + bv.w;
        *(float4*)&xrow[e0] = ov;
    }
}

__global__ void ln_kernel_h(const float* __restrict__ in, const float* __restrict__ g,
                            const float* __restrict__ bpar, __half* __restrict__ out,
                            float* gmax_init)
{
    int warp = threadIdx.x >> 5, lane = threadIdx.x & 31;
    int r = blockIdx.x * 8 + warp;
    if (gmax_init && r == 0 && lane == 0) *gmax_init = -3.4e38f;
    const float* row = in + (size_t)r * cE;
    float vals[16];
    float sum = 0.f;
#pragma unroll
    for (int i = 0; i < 4; i++) {
        float4 v = *(const float4*)&row[i * 128 + lane * 4];
        vals[i * 4 + 0] = v.x; vals[i * 4 + 1] = v.y;
        vals[i * 4 + 2] = v.z; vals[i * 4 + 3] = v.w;
        sum += v.x + v.y + v.z + v.w;
    }
    float mu = warp_sum(sum) * (1.f / cE);
    float vs = 0.f;
#pragma unroll
    for (int i = 0; i < 16; i++) { float d = vals[i] - mu; vs += d * d; }
    float rstd = rsqrtf(warp_sum(vs) * (1.f / cE) + 1e-5f);
    __half* orow = out + (size_t)r * cE;
#pragma unroll
    for (int i = 0; i < 4; i++) {
        int e0 = i * 128 + lane * 4;
        float4 gv = *(const float4*)&g[e0];
        float4 bv = *(const float4*)&bpar[e0];
        float o0 = (vals[i * 4 + 0] - mu) * rstd * gv.x + bv.x;
        float o1 = (vals[i * 4 + 1] - mu) * rstd * gv.y + bv.y;
        float o2 = (vals[i * 4 + 2] - mu) * rstd * gv.z + bv.z;
        float o3 = (vals[i * 4 + 3] - mu) * rstd * gv.w + bv.w;
        *(__half2*)&orow[e0]     = __floats2half2_rn(o0, o1);
        *(__half2*)&orow[e0 + 2] = __floats2half2_rn(o2, o3);
    }
}

constexpr int AST2 = 24;
constexpr int BST2 = 136;
constexpr int HSTG = 4;
constexpr int ASZ = 128 * AST2;
constexpr int BSZ = 16 * BST2;
constexpr size_t GEMM_SMEM_BYTES = (size_t)HSTG * (ASZ + BSZ) * 2;

__global__ __launch_bounds__(256, 2)
void gemm_f16(const __half* __restrict__ A, const __half* __restrict__ Bm,
              const float* __restrict__ bias, const float* __restrict__ res,
              float* __restrict__ C, __half* __restrict__ Ch, int N, int K, int act)
{
    extern __shared__ __half hsm[];
    __half* Asm = hsm;
    __half* Bsm = hsm + (size_t)HSTG * ASZ;

    int tid = threadIdx.x;
    int warp = tid >> 5, lane = tid & 31;
    int wm = warp >> 2, wn = warp & 3;
    int g = lane >> 2, t4 = lane & 3;
    int row0 = blockIdx.y * 128, col0 = blockIdx.x * 128;

    int arow = tid >> 1, ac8 = (tid & 1) * 8;
    int brow = tid >> 4, bc8 = (tid & 15) * 8;

    const __half* Ap = A + (size_t)(row0 + arow) * K + ac8;
    const __half* Bp = Bm + (size_t)brow * N + col0 + bc8;
    unsigned aBase = (unsigned)__cvta_generic_to_shared(Asm) + (unsigned)(arow * AST2 + ac8) * 2;
    unsigned bBase = (unsigned)__cvta_generic_to_shared(Bsm) + (unsigned)(brow * BST2 + bc8) * 2;
    unsigned aLds = (unsigned)__cvta_generic_to_shared(Asm);
    unsigned bLds = (unsigned)__cvta_generic_to_shared(Bsm);

    int nT = K >> 4;

    auto issue = [&](int t) {
        int s = t & (HSTG - 1);
        cp16(aBase + (unsigned)s * (ASZ * 2), Ap + (size_t)t * 16);
        cp16(bBase + (unsigned)s * (BSZ * 2), Bp + (size_t)(t * 16) * N);
    };

    float acc[4][4][4];
#pragma unroll
    for (int mi = 0; mi < 4; mi++)
#pragma unroll
        for (int ni = 0; ni < 4; ni++)
#pragma unroll
            for (int q = 0; q < 4; q++) acc[mi][ni][q] = 0.f;

    issue(0); cp_commit();
    issue(1); cp_commit();
    issue(2); cp_commit();

    int aRowSel = lane & 15;
    int aColSel = (lane >> 4) * 8;
    int bRowSel = lane & 15;

    for (int t = 0; t < nT; t++) {
        cp_wait<2>();
        __syncthreads();
        if (t + 3 < nT) issue(t + 3);
        cp_commit();
        int s = t & (HSTG - 1);
        unsigned aS = aLds + (unsigned)s * (ASZ * 2);
        unsigned bS = bLds + (unsigned)s * (BSZ * 2);

        unsigned afr[4][4];
#pragma unroll
        for (int mi = 0; mi < 4; mi++) {
            int row = wm * 64 + mi * 16 + aRowSel;
            ldsm_x4(afr[mi][0], afr[mi][1], afr[mi][2], afr[mi][3],
                    aS + (unsigned)(row * AST2 + aColSel) * 2);
        }
        unsigned bfr[4][2];
#pragma unroll
        for (int ni = 0; ni < 4; ni++) {
            int n = wn * 32 + ni * 8;
            ldsm_x2t(bfr[ni][0], bfr[ni][1], bS + (unsigned)(bRowSel * BST2 + n) * 2);
        }
#pragma unroll
        for (int ni = 0; ni < 4; ni++)
#pragma unroll
            for (int mi = 0; mi < 4; mi++)
                mma_f16(acc[mi][ni], afr[mi], bfr[ni][0], bfr[ni][1]);
    }

#pragma unroll
    for (int mi = 0; mi < 4; mi++) {
#pragma unroll
        for (int ni = 0; ni < 4; ni++) {
            int row = row0 + wm * 64 + mi * 16 + g;
            int col = col0 + wn * 32 + ni * 8 + 2 * t4;
#pragma unroll
            for (int half_ = 0; half_ < 2; half_++) {
                int r = row + half_ * 8;
                float v0 = acc[mi][ni][half_ * 2 + 0];
                float v1 = acc[mi][ni][half_ * 2 + 1];
                if (bias) { v0 += bias[col]; v1 += bias[col + 1]; }
                if (act) {
                    v0 = 0.5f * v0 * (1.f + erff(v0 * 0.70710678118654752f));
                    v1 = 0.5f * v1 * (1.f + erff(v1 * 0.70710678118654752f));
                }
                if (res) {
                    v0 += res[(size_t)r * N + col];
                    v1 += res[(size_t)r * N + col + 1];
                }
                if (C)  *(float2*)&C[(size_t)r * N + col] = make_float2(v0, v1);
                if (Ch) *(__half2*)&Ch[(size_t)r * N + col] = __floats2half2_rn(v0, v1);
            }
        }
    }
}

__global__ __launch_bounds__(256, 2)
void gemm_qkv(const __half* __restrict__ A, const __half* __restrict__ Bq,
              const __half* __restrict__ Bk, const __half* __restrict__ Bv,
              __half* __restrict__ Cq, __half* __restrict__ Ck, __half* __restrict__ Cv)
{
    constexpr int N = cE, K = cE;
    extern __shared__ __half hsm[];
    __half* Asm = hsm;
    __half* Bsm = hsm + (size_t)HSTG * ASZ;

    int tid = threadIdx.x;
    int warp = tid >> 5, lane = tid & 31;
    int wm = warp >> 2, wn = warp & 3;
    int g = lane >> 2, t4 = lane & 3;
    int bx = blockIdx.x;
    int sel = bx >> 2;
    const __half* Bm = sel == 0 ? Bq : (sel == 1 ? Bk : Bv);
    __half* C = sel == 0 ? Cq : (sel == 1 ? Ck : Cv);
    int row0 = blockIdx.y * 128, col0 = (bx & 3) * 128;

    int arow = tid >> 1, ac8 = (tid & 1) * 8;
    int brow = tid >> 4, bc8 = (tid & 15) * 8;

    const __half* Ap = A + (size_t)(row0 + arow) * K + ac8;
    const __half* Bp = Bm + (size_t)brow * N + col0 + bc8;
    unsigned aBase = (unsigned)__cvta_generic_to_shared(Asm) + (unsigned)(arow * AST2 + ac8) * 2;
    unsigned bBase = (unsigned)__cvta_generic_to_shared(Bsm) + (unsigned)(brow * BST2 + bc8) * 2;
    unsigned aLds = (unsigned)__cvta_generic_to_shared(Asm);
    unsigned bLds = (unsigned)__cvta_generic_to_shared(Bsm);

    int nT = K >> 4;

    auto issue = [&](int t) {
        int s = t & (HSTG - 1);
        cp16(aBase + (unsigned)s * (ASZ * 2), Ap + (size_t)t * 16);
        cp16(bBase + (unsigned)s * (BSZ * 2), Bp + (size_t)(t * 16) * N);
    };

    float acc[4][4][4];
#pragma unroll
    for (int mi = 0; mi < 4; mi++)
#pragma unroll
        for (int ni = 0; ni < 4; ni++)
#pragma unroll
            for (int q = 0; q < 4; q++) acc[mi][ni][q] = 0.f;

    issue(0); cp_commit();
    issue(1); cp_commit();
    issue(2); cp_commit();

    int aRowSel = lane & 15;
    int aColSel = (lane >> 4) * 8;
    int bRowSel = lane & 15;

    for (int t = 0; t < nT; t++) {
        cp_wait<2>();
        __syncthreads();
        if (t + 3 < nT) issue(t + 3);
        cp_commit();
        int s = t & (HSTG - 1);
        unsigned aS = aLds + (unsigned)s * (ASZ * 2);
        unsigned bS = bLds + (unsigned)s * (BSZ * 2);

        unsigned afr[4][4];
#pragma unroll
        for (int mi = 0; mi < 4; mi++) {
            int row = wm * 64 + mi * 16 + aRowSel;
            ldsm_x4(afr[mi][0], afr[mi][1], afr[mi][2], afr[mi][3],
                    aS + (unsigned)(row * AST2 + aColSel) * 2);
        }
        unsigned bfr[4][2];
#pragma unroll
        for (int ni = 0; ni < 4; ni++) {
            int n = wn * 32 + ni * 8;
            ldsm_x2t(bfr[ni][0], bfr[ni][1], bS + (unsigned)(bRowSel * BST2 + n) * 2);
        }
#pragma unroll
        for (int ni = 0; ni < 4; ni++)
#pragma unroll
            for (int mi = 0; mi < 4; mi++)
                mma_f16(acc[mi][ni], afr[mi], bfr[ni][0], bfr[ni][1]);
    }

#pragma unroll
    for (int mi = 0; mi < 4; mi++) {
#pragma unroll
        for (int ni = 0; ni < 4; ni++) {
            int row = row0 + wm * 64 + mi * 16 + g;
            int col = col0 + wn * 32 + ni * 8 + 2 * t4;
#pragma unroll
            for (int half_ = 0; half_ < 2; half_++) {
                int r = row + half_ * 8;
                *(__half2*)&C[(size_t)r * N + col] =
                    __floats2half2_rn(acc[mi][ni][half_ * 2 + 0], acc[mi][ni][half_ * 2 + 1]);
            }
        }
    }
}

constexpr int XST = 72;
constexpr size_t FEATM_BYTES = (size_t)(128 + 128 + 256) * XST * 2 + (128 * 2 + 8) * 4;

__global__ void feat_qk_mma(const __half* __restrict__ qH, const __half* __restrict__ kH,
                            const __half* __restrict__ projH, __half* __restrict__ qfh,
                            __half* __restrict__ kfh, float* __restrict__ kdiag,
                            float* __restrict__ gmax)
{
    extern __shared__ __half fh[];
    __half* xq = fh;
    __half* xk = xq + 128 * XST;
    __half* pj = xk + 128 * XST;
    float* ssqq = (float*)(pj + 256 * XST);
    float* ssqk = ssqq + 128;
    float* wmax = ssqk + 128;

    int s0 = blockIdx.x * 128;
    int bh = blockIdx.y;
    int b = bh / cH, h = bh % cH;
    int tid = threadIdx.x, warp = tid >> 5, lane = tid & 31;

    for (int i = tid; i < 128 * 8; i += 256) {
        int r = i >> 3, c = (i & 7) * 8;
        size_t gi = (size_t)(b * cS + s0 + r) * cE + h * cDH + c;
        *(uint4*)&xq[r * XST + c] = *(const uint4*)&qH[gi];
        *(uint4*)&xk[r * XST + c] = *(const uint4*)&kH[gi];
    }
    for (int i = tid; i < 256 * 8; i += 256) {
        int r = i >> 3, c = (i & 7) * 8;
        *(uint4*)&pj[r * XST + c] = *(const uint4*)&projH[(size_t)r * cDH + c];
    }
    __syncthreads();
    {
        int r = tid & 127;
        const __half* xp = (tid < 128) ? &xq[r * XST] : &xk[r * XST];
        float acc = 0.f;
#pragma unroll
        for (int d = 0; d < 64; d += 2) {
            float2 f = __half22float2(*(const __half2*)&xp[d]);
            acc += f.x * f.x + f.y * f.y;
        }
        if (tid < 128) ssqq[r] = acc; else ssqk[r] = acc;
    }
    __syncthreads();

    unsigned xqb = (unsigned)__cvta_generic_to_shared(xq);
    unsigned xkb = (unsigned)__cvta_generic_to_shared(xk);
    unsigned pjb = (unsigned)__cvta_generic_to_shared(pj);

    int l16 = lane & 15, lhi = lane >> 4;
    int lq = lane & 7, grp = lane >> 3;
    int g = lane >> 2, t4 = lane & 3;
    int m0 = warp * 16;
    const float dn = 0.35355339059327373f;
    const float dn2 = 0.5f * dn * dn;

    int rowlo = m0 + g, rowhi = rowlo + 8;
    size_t orow_lo = ((size_t)bh * cS + s0 + rowlo) * cM;
    size_t orow_hi = ((size_t)bh * cS + s0 + rowhi) * cM;

    {
        float acc[32][4];
#pragma unroll
        for (int j = 0; j < 32; j++)
#pragma unroll
            for (int q = 0; q < 4; q++) acc[j][q] = 0.f;

#pragma unroll
        for (int ks = 0; ks < 4; ks++) {
            int k0 = ks * 16;
            unsigned a4[4];
            ldsm_x4(a4[0], a4[1], a4[2], a4[3],
                    xqb + (unsigned)((m0 + l16) * XST + k0 + 8 * lhi) * 2);
#pragma unroll
            for (int nf = 0; nf < 16; nf++) {
                unsigned b4[4];
                int nrow = nf * 16 + lq + ((grp & 2) ? 8 : 0);
                int kcol = k0 + ((grp & 1) ? 8 : 0);
                ldsm_x4(b4[0], b4[1], b4[2], b4[3], pjb + (unsigned)(nrow * XST + kcol) * 2);
                mma_f16(acc[2 * nf],     a4, b4[0], b4[1]);
                mma_f16(acc[2 * nf + 1], a4, b4[2], b4[3]);
            }
        }
        float mlo = acc[0][0], mhi = acc[0][2];
#pragma unroll
        for (int j = 0; j < 32; j++) {
            mlo = fmaxf(mlo, fmaxf(acc[j][0], acc[j][1]));
            mhi = fmaxf(mhi, fmaxf(acc[j][2], acc[j][3]));
        }
#pragma unroll
        for (int s = 1; s < 4; s <<= 1) {
            mlo = fmaxf(mlo, __shfl_xor_sync(0xffffffff, mlo, s));
            mhi = fmaxf(mhi, __shfl_xor_sync(0xffffffff, mhi, s));
        }
        float elo = ssqq[rowlo] * dn2 + mlo * dn;
        float ehi = ssqq[rowhi] * dn2 + mhi * dn;
#pragma unroll
        for (int j = 0; j < 32; j++) {
            int col = j * 8 + 2 * t4;
            float v0 = 0.0625f * (__expf(acc[j][0] * dn - elo) + 1e-4f);
            float v1 = 0.0625f * (__expf(acc[j][1] * dn - elo) + 1e-4f);
            float v2 = 0.0625f * (__expf(acc[j][2] * dn - ehi) + 1e-4f);
            float v3 = 0.0625f * (__expf(acc[j][3] * dn - ehi) + 1e-4f);
            *(__half2*)&qfh[orow_lo + col] = __floats2half2_rn(v0, v1);
            *(__half2*)&qfh[orow_hi + col] = __floats2half2_rn(v2, v3);
        }
    }

    {
        float acc[32][4];
#pragma unroll
        for (int j = 0; j < 32; j++)
#pragma unroll
            for (int q = 0; q < 4; q++) acc[j][q] = 0.f;

#pragma unroll
        for (int ks = 0; ks < 4; ks++) {
            int k0 = ks * 16;
            unsigned a4[4];
            ldsm_x4(a4[0], a4[1], a4[2], a4[3],
                    xkb + (unsigned)((m0 + l16) * XST + k0 + 8 * lhi) * 2);
#pragma unroll
            for (int nf = 0; nf < 16; nf++) {
                unsigned b4[4];
                int nrow = nf * 16 + lq + ((grp & 2) ? 8 : 0);
                int kcol = k0 + ((grp & 1) ? 8 : 0);
                ldsm_x4(b4[0], b4[1], b4[2], b4[3], pjb + (unsigned)(nrow * XST + kcol) * 2);
                mma_f16(acc[2 * nf],     a4, b4[0], b4[1]);
                mma_f16(acc[2 * nf + 1], a4, b4[2], b4[3]);
            }
        }
        float tm = acc[0][0];
#pragma unroll
        for (int j = 0; j < 32; j++) {
            int col = j * 8 + 2 * t4;
            float v0 = acc[j][0] * dn, v1 = acc[j][1] * dn;
            float v2 = acc[j][2] * dn, v3 = acc[j][3] * dn;
            *(__half2*)&kfh[orow_lo + col] = __floats2half2_rn(v0, v1);
            *(__half2*)&kfh[orow_hi + col] = __floats2half2_rn(v2, v3);
            tm = fmaxf(tm, fmaxf(fmaxf(acc[j][0], acc[j][1]), fmaxf(acc[j][2], acc[j][3])));
        }
#pragma unroll
        for (int s = 16; s > 0; s >>= 1) tm = fmaxf(tm, __shfl_xor_sync(0xffffffff, tm, s));
        if (lane == 0) wmax[warp] = tm * dn;
    }
    if (tid < 128) kdiag[(size_t)bh * cS + s0 + tid] = ssqk[tid] * dn2;
    __syncthreads();
    if (tid == 0) {
        float mx = wmax[0];
#pragma unroll
        for (int w = 1; w < 8; w++) mx = fmaxf(mx, wmax[w]);
        atomicMaxFloat(gmax, mx);
    }
}

constexpr int CKST = 264;
constexpr int CVST = 88;
constexpr size_t CHUNK_SMEM_BYTES = (size_t)(128 * CKST + 128 * CVST) * 2 + 128 * 4;

__global__ void attn_chunk_mma(const float* __restrict__ kdiag, const float* __restrict__ gmax,
                               const __half* __restrict__ vH, __half* __restrict__ kfh,
                               float* __restrict__ kvsum, float* __restrict__ zc)
{
    extern __shared__ __half csm[];
    __half* kfs = csm;
    __half* vsm = kfs + 128 * CKST;
    float* kdsh = (float*)(vsm + 128 * CVST);

    int ch = blockIdx.x, bh = blockIdx.y;
    int b = bh / cH, h = bh % cH;
    int tid = threadIdx.x, warp = tid >> 5, lane = tid & 31;
    int c0 = ch * cCHUNK;

    __half* kg = kfh + ((size_t)bh * cS + c0) * cM;
    for (int i = tid; i < 128 * 32; i += 256) {
        int r = i >> 5, c = (i & 31) * 8;
        *(uint4*)&kfs[r * CKST + c] = *(const uint4*)&kg[(size_t)r * cM + c];
    }
    const __half* vg = vH + (size_t)(b * cS + c0) * cE + h * cDH;
    for (int i = tid; i < 128 * 8; i += 256) {
        int r = i >> 3, c = (i & 7) * 8;
        *(uint4*)&vsm[r * CVST + c] = *(const uint4*)&vg[(size_t)r * cE + c];
    }
    for (int i = tid; i < 128 * 16; i += 256) {
        int r = i >> 4, c = 64 + (i & 15);
        vsm[r * CVST + c] = (c == 64) ? __float2half(1.f) : __float2half(0.f);
    }
    if (tid < 128) kdsh[tid] = kdiag[(size_t)bh * cS + c0 + tid];
    float gm = *gmax;
    __syncthreads();

    for (int i = tid; i < 128 * 256; i += 256) {
        int s = i >> 8, m = i & 255;
        float raw = __half2float(kfs[s * CKST + m]);
        float kv = 0.0625f * (__expf(raw - kdsh[s] - gm) + 1e-4f);
        __half hv = __float2half(kv);
        kfs[s * CKST + m] = hv;
        kg[(size_t)s * cM + m] = hv;
    }
    __syncthreads();

    unsigned kfb = (unsigned)__cvta_generic_to_shared(kfs);
    unsigned vbb = (unsigned)__cvta_generic_to_shared(vsm);
    int lq = lane & 7, grp = lane >> 3;
    int g = lane >> 2, t4 = lane & 3;
    int m0 = warp * 32;

    float acc[2][9][4];
#pragma unroll
    for (int mi = 0; mi < 2; mi++)
#pragma unroll
        for (int j = 0; j < 9; j++)
#pragma unroll
            for (int q = 0; q < 4; q++) acc[mi][j][q] = 0.f;

#pragma unroll
    for (int ks = 0; ks < 8; ks++) {
        int k0 = ks * 16;
        int krow = k0 + lq + ((grp & 1) ? 8 : 0);
        unsigned afr[2][4];
#pragma unroll
        for (int mi = 0; mi < 2; mi++) {
            int mcol = m0 + mi * 16 + ((grp & 2) ? 8 : 0);
            unsigned t0, t1, t2, t3;
            ldsm_x4t(t0, t1, t2, t3, kfb + (unsigned)(krow * CKST + mcol) * 2);
            afr[mi][0] = t0; afr[mi][1] = t2; afr[mi][2] = t1; afr[mi][3] = t3;
        }
        unsigned bf[5][4];
#pragma unroll
        for (int nf = 0; nf < 5; nf++) {
            int ncol = nf * 16 + ((grp & 2) ? 8 : 0);
            ldsm_x4t(bf[nf][0], bf[nf][1], bf[nf][2], bf[nf][3],
                     vbb + (unsigned)(krow * CVST + ncol) * 2);
        }
#pragma unroll
        for (int j = 0; j < 9; j++) {
            int nf = j >> 1, p = j & 1;
            mma_f16(acc[0][j], afr[0], bf[nf][p * 2], bf[nf][p * 2 + 1]);
            mma_f16(acc[1][j], afr[1], bf[nf][p * 2], bf[nf][p * 2 + 1]);
        }
    }

#pragma unroll
    for (int mi = 0; mi < 2; mi++) {
        int rlo = m0 + mi * 16 + g, rhi = rlo + 8;
        float* klo = kvsum + (((size_t)bh * cNC + ch) * cM + rlo) * cDH;
        float* khi = kvsum + (((size_t)bh * cNC + ch) * cM + rhi) * cDH;
#pragma unroll
        for (int nf = 0; nf < 8; nf++) {
            int col = nf * 8 + 2 * t4;
            *(float2*)&klo[col] = make_float2(acc[mi][nf][0], acc[mi][nf][1]);
            *(float2*)&khi[col] = make_float2(acc[mi][nf][2], acc[mi][nf][3]);
        }
        if (t4 == 0) {
            zc[((size_t)bh * cNC + ch) * cM + rlo] = acc[mi][8][0];
            zc[((size_t)bh * cNC + ch) * cM + rhi] = acc[mi][8][2];
        }
    }
}

__global__ void attn_prefix(const float* __restrict__ kvsum, const float* __restrict__ zc,
                            __half* __restrict__ sphg)
{
    int bh = blockIdx.x, ds = blockIdx.y;
    int m = threadIdx.x;
    int d0 = ds * 4;
    float carry[4] = {0.f, 0.f, 0.f, 0.f};
    float zcarry = 0.f;
    for (int c = 0; c < cNC; c++) {
        const float* p = kvsum + (((size_t)bh * cNC + c) * cM + m) * cDH + d0;
        __half* sp = sphg + (((size_t)bh * cNC + c) * cM + m) * 72 + d0;
        float4 t = *(const float4*)p;
        *(__half2*)&sp[0] = __floats2half2_rn(carry[0], carry[1]);
        *(__half2*)&sp[2] = __floats2half2_rn(carry[2], carry[3]);
        carry[0] += t.x; carry[1] += t.y; carry[2] += t.z; carry[3] += t.w;
        if (ds == 0) {
            __half* spz = sphg + (((size_t)bh * cNC + c) * cM + m) * 72;
            spz[64] = __float2half(zcarry);
#pragma unroll
            for (int j = 65; j < 72; j++) spz[j] = __float2half(0.f);
            zcarry += zc[((size_t)bh * cNC + c) * cM + m];
        }
    }
}

constexpr int QST = 264;
constexpr int ASH_ST = 136;
constexpr int VST = 88;
constexpr size_t ATT2_HALVES = (size_t)128 * QST * 2 + 128 * VST + 256 * VST;
constexpr size_t ATT2_BYTES = ATT2_HALVES * 2;

__global__ void attn_out(const __half* __restrict__ qfh, const __half* __restrict__ kfh,
                         const __half* __restrict__ vH, const __half* __restrict__ sphg,
                         __half* __restrict__ oH)
{
    extern __shared__ __half hsm2[];
    __half* qh  = hsm2;
    __half* kh  = qh + 128 * QST;
    __half* vh  = kh + 128 * QST;
    __half* sph = vh + 128 * VST;

    int ch = blockIdx.x, bh = blockIdx.y;
    int b = bh / cH, h = bh % cH;
    int tid = threadIdx.x, warp = tid >> 5, lane = tid & 31;
    int c0 = ch * cCHUNK;

    const __half* qg = qfh + ((size_t)bh * cS + c0) * cM;
    const __half* kg = kfh + ((size_t)bh * cS + c0) * cM;
    for (int i = tid; i < 128 * 32; i += 256) {
        int r = i >> 5, c = (i & 31) * 8;
        *(uint4*)&qh[r * QST + c] = *(const uint4*)&qg[(size_t)r * cM + c];
        *(uint4*)&kh[r * QST + c] = *(const uint4*)&kg[(size_t)r * cM + c];
    }
    const __half* vg = vH + (size_t)(b * cS + c0) * cE + h * cDH;
    for (int i = tid; i < 128 * 8; i += 256) {
        int r = i >> 3, c = (i & 7) * 8;
        *(uint4*)&vh[r * VST + c] = *(const uint4*)&vg[(size_t)r * cE + c];
    }
    for (int i = tid; i < 128 * 24; i += 256) {
        int r = i / 24, c = i % 24;
        vh[r * VST + 64 + c] = (c == 0) ? __float2half(1.f) : __float2half(0.f);
    }
    const __half* sg = sphg + ((size_t)bh * cNC + ch) * cM * 72;
    for (int i = tid; i < 256 * 9; i += 256) {
        int r = i / 9, c = (i % 9) * 8;
        *(uint4*)&sph[r * VST + c] = *(const uint4*)&sg[(size_t)r * 72 + c];
    }
    for (int i = tid; i < 256 * 16; i += 256) {
        int r = i >> 4, c = i & 15;
        sph[r * VST + 72 + c] = __float2half(0.f);
    }
    __syncthreads();

    unsigned qb = (unsigned)__cvta_generic_to_shared(qh);
    unsigned kb = (unsigned)__cvta_generic_to_shared(kh);
    unsigned vb = (unsigned)__cvta_generic_to_shared(vh);
    unsigned sb = (unsigned)__cvta_generic_to_shared(sph);

    int l16 = lane & 15, lhi = lane >> 4;
    int lq = lane & 7, grp = lane >> 3;
    int g = lane >> 2, t4 = lane & 3;

    {
        int wm = warp >> 2, wn = warp & 3;
        float accA[4][4][4];
#pragma unroll
        for (int mi = 0; mi < 4; mi++)
#pragma unroll
            for (int ni = 0; ni < 4; ni++)
#pragma unroll
                for (int q = 0; q < 4; q++) accA[mi][ni][q] = 0.f;

        for (int ks = 0; ks < 16; ks++) {
            int k0 = ks * 16;
            unsigned af[4][4];
#pragma unroll
            for (int mi = 0; mi < 4; mi++)
                ldsm_x4(af[mi][0], af[mi][1], af[mi][2], af[mi][3],
                        qb + (unsigned)((wm * 64 + mi * 16 + l16) * QST + k0 + 8 * lhi) * 2);
            unsigned bfA[2][4];
#pragma unroll
            for (int g16 = 0; g16 < 2; g16++) {
                int n0 = wn * 32 + g16 * 16;
                int nrow = n0 + lq + ((grp & 2) ? 8 : 0);
                int kcol = k0 + ((grp & 1) ? 8 : 0);
                ldsm_x4(bfA[g16][0], bfA[g16][1], bfA[g16][2], bfA[g16][3],
                        kb + (unsigned)(nrow * QST + kcol) * 2);
            }
#pragma unroll
            for (int ni = 0; ni < 4; ni++) {
                unsigned b0 = bfA[ni >> 1][(ni & 1) * 2];
                unsigned b1 = bfA[ni >> 1][(ni & 1) * 2 + 1];
#pragma unroll
                for (int mi = 0; mi < 4; mi++)
                    mma_f16(accA[mi][ni], af[mi], b0, b1);
            }
        }
        __syncthreads();
#pragma unroll
        for (int mi = 0; mi < 4; mi++) {
#pragma unroll
            for (int ni = 0; ni < 4; ni++) {
                int row = wm * 64 + mi * 16 + g;
                int col = wn * 32 + ni * 8 + 2 * t4;
                float a0 = (col <= row) ? accA[mi][ni][0] : 0.f;
                float a1 = (col + 1 <= row) ? accA[mi][ni][1] : 0.f;
                *(__half2*)&kh[row * ASH_ST + col] = __floats2half2_rn(a0, a1);
                int row2 = row + 8;
                float a2 = (col <= row2) ? accA[mi][ni][2] : 0.f;
                float a3 = (col + 1 <= row2) ? accA[mi][ni][3] : 0.f;
                *(__half2*)&kh[row2 * ASH_ST + col] = __floats2half2_rn(a2, a3);
            }
        }
        __syncthreads();
    }

    float accN[9][4];
#pragma unroll
    for (int j = 0; j < 9; j++)
#pragma unroll
        for (int q = 0; q < 4; q++) accN[j][q] = 0.f;

    int m0 = warp * 16;
    for (int ks = 0; ks < 16; ks++) {
        int k0 = ks * 16;
        unsigned af4[4];
        ldsm_x4(af4[0], af4[1], af4[2], af4[3],
                qb + (unsigned)((m0 + l16) * QST + k0 + 8 * lhi) * 2);
        unsigned bf[5][4];
        int krow = k0 + lq + ((grp & 1) ? 8 : 0);
#pragma unroll
        for (int nf = 0; nf < 5; nf++) {
            int ncol = nf * 16 + ((grp & 2) ? 8 : 0);
            ldsm_x4t(bf[nf][0], bf[nf][1], bf[nf][2], bf[nf][3],
                     sb + (unsigned)(krow * VST + ncol) * 2);
        }
#pragma unroll
        for (int j = 0; j < 9; j++) {
            int nf = j >> 1, p = j & 1;
            mma_f16(accN[j], af4, bf[nf][p * 2], bf[nf][p * 2 + 1]);
        }
    }
    for (int ks = 0; ks < 8; ks++) {
        int k0 = ks * 16;
        unsigned af4[4];
        ldsm_x4(af4[0], af4[1], af4[2], af4[3],
                kb + (unsigned)((m0 + l16) * ASH_ST + k0 + 8 * lhi) * 2);
        unsigned bf[5][4];
        int krow = k0 + lq + ((grp & 1) ? 8 : 0);
#pragma unroll
        for (int nf = 0; nf < 5; nf++) {
            int ncol = nf * 16 + ((grp & 2) ? 8 : 0);
            ldsm_x4t(bf[nf][0], bf[nf][1], bf[nf][2], bf[nf][3],
                     vb + (unsigned)(krow * VST + ncol) * 2);
        }
#pragma unroll
        for (int j = 0; j < 9; j++) {
            int nf = j >> 1, p = j & 1;
            mma_f16(accN[j], af4, bf[nf][p * 2], bf[nf][p * 2 + 1]);
        }
    }

    float denlo = __shfl_sync(0xffffffff, accN[8][0], lane & ~3);
    float denhi = __shfl_sync(0xffffffff, accN[8][2], lane & ~3);
    float invlo = 1.f / (denlo + 1e-6f);
    float invhi = 1.f / (denhi + 1e-6f);
    int rowlo = m0 + g, rowhi = rowlo + 8;
    __half* olo = oH + (size_t)(b * cS + c0 + rowlo) * cE + h * cDH;
    __half* ohi = oH + (size_t)(b * cS + c0 + rowhi) * cE + h * cDH;
#pragma unroll
    for (int nf = 0; nf < 8; nf++) {
        int col = nf * 8 + 2 * t4;
        *(__half2*)&olo[col] = __floats2half2_rn(accN[nf][0] * invlo, accN[nf][1] * invlo);
        *(__half2*)&ohi[col] = __floats2half2_rn(accN[nf][2] * invhi, accN[nf][3] * invhi);
    }
}

extern "C" void kernel_launch(void* const* d_in, const int* in_sizes, int n_in,
                              void* d_out, int out_size)
{
    const int*   src  = (const int*)d_in[0];
    const float* emb  = (const float*)d_in[2];
    const float* lng  = (const float*)d_in[3];
    const float* lnb  = (const float*)d_in[4];
    const float* Wq   = (const float*)d_in[5];
    const float* Wk   = (const float*)d_in[6];
    const float* Wv   = (const float*)d_in[7];
    const float* Wo   = (const float*)d_in[8];
    const float* ln1g = (const float*)d_in[9];
    const float* ln1b = (const float*)d_in[10];
    const float* W1   = (const float*)d_in[11];
    const float* b1   = (const float*)d_in[12];
    const float* W2   = (const float*)d_in[13];
    const float* b2   = (const float*)d_in[14];
    const float* ln2g = (const float*)d_in[15];
    const float* ln2b = (const float*)d_in[16];
    const float* proj = (const float*)d_in[17];
    const float* fcw  = (const float*)d_in[18];
    const float* fcb  = (const float*)d_in[19];
    float* out = (float*)d_out;

    float* sc = nullptr;
    cudaGetSymbolAddress((void**)&sc, g_scratch);
    __half* sh = nullptr;
    cudaGetSymbolAddress((void**)&sh, g_scratch_h);

    float* x    = sc + OFF_X;
    float* kd   = sc + OFF_KD;
    float* kvs  = sc + OFF_KV;
    float* zcb  = sc + OFF_ZC;
    float* gmax = sc + OFF_GMAX;

    __half* hH   = sh + HOFF_H;
    __half* oH   = sh + HOFF_O;
    __half* ffnH = sh + HOFF_FFN;
    __half* xH   = sh + HOFF_XH;
    __half* vH   = sh + HOFF_VH;
    __half* qH   = sh + HOFF_QH;
    __half* kH   = sh + HOFF_KH;
    __half* qfh  = sh + HOFF_QFH;
    __half* kfh  = sh + HOFF_KFH;
    __half* sphg = sh + HOFF_SPH;
    __half* pjH  = sh + HOFF_PJ;
    __half* WqH  = sh + HOFF_WQ;
    __half* WkH  = sh + HOFF_WK;
    __half* WvH  = sh + HOFF_WV;
    __half* WoH  = sh + HOFF_WO;
    __half* W1H  = sh + HOFF_W1;
    __half* W2H  = sh + HOFF_W2;
    __half* fcwH = sh + HOFF_FCW;

    cudaFuncSetAttribute(gemm_f16, cudaFuncAttributeMaxDynamicSharedMemorySize, (int)GEMM_SMEM_BYTES);
    cudaFuncSetAttribute(gemm_qkv, cudaFuncAttributeMaxDynamicSharedMemorySize, (int)GEMM_SMEM_BYTES);
    cudaFuncSetAttribute(attn_out, cudaFuncAttributeMaxDynamicSharedMemorySize, (int)ATT2_BYTES);
    cudaFuncSetAttribute(feat_qk_mma, cudaFuncAttributeMaxDynamicSharedMemorySize, (int)FEATM_BYTES);
    cudaFuncSetAttribute(attn_chunk_mma, cudaFuncAttributeMaxDynamicSharedMemorySize, (int)CHUNK_SMEM_BYTES);

    int nWsm = cL * cE * cE / 4;
    int nWff = cL * cE * 4 * cE / 4;
    int nFcw = cE * cV / 4;
    int nPj  = cL * cM * cDH / 4;
    f2h4_kernel<<<dim3(256, 4), 256>>>(Wq, Wk, Wv, Wo, WqH, WkH, WvH, WoH, nWsm);
    f2h4_kernel<<<dim3(512, 2), 256>>>(W1, W2, W1, W2, W1H, W2H, W1H, W2H, nWff);
    f2h2_kernel<<<dim3(1024, 2), 256>>>(fcw, proj, fcwH, pjH, nFcw, nPj);

    embed_ln_kernel<<<cBS / 8, 256>>>(src, emb, lng, lnb, x);

    dim3 g512(cE / 128, cBS / 128);
    dim3 gF1(4 * cE / 128, cBS / 128);
    dim3 gQKV(12, cBS / 128);
    dim3 gFeatM(cS / 128, cBH);
    dim3 gChunk(cNC, cBH);
    dim3 gPfx(cBH, 16);

    for (int l = 0; l < cL; l++) {
        ln_kernel_h<<<cBS / 8, 256>>>(x, ln1g + (size_t)l * cE, ln1b + (size_t)l * cE, hH, gmax);
        gemm_qkv<<<gQKV, 256, GEMM_SMEM_BYTES>>>(hH, WqH + (size_t)l * cE * cE,
                                                 WkH + (size_t)l * cE * cE,
                                                 WvH + (size_t)l * cE * cE, qH, kH, vH);

        feat_qk_mma<<<gFeatM, 256, FEATM_BYTES>>>(qH, kH, pjH + (size_t)l * cM * cDH,
                                                  qfh, kfh, kd, gmax);

        attn_chunk_mma<<<gChunk, 256, CHUNK_SMEM_BYTES>>>(kd, gmax, vH, kfh, kvs, zcb);
        attn_prefix<<<gPfx, 256>>>(kvs, zcb, sphg);
        attn_out<<<gChunk, 256, ATT2_BYTES>>>(qfh, kfh, vH, sphg, oH);

        gemm_f16<<<g512, 256, GEMM_SMEM_BYTES>>>(oH, WoH + (size_t)l * cE * cE,
                                                 nullptr, x, x, nullptr, cE, cE, 0);

        ln_kernel_h<<<cBS / 8, 256>>>(x, ln2g + (size_t)l * cE, ln2b + (size_t)l * cE, hH, nullptr);
        gemm_f16<<<gF1, 256, GEMM_SMEM_BYTES>>>(hH, W1H + (size_t)l * cE * 4 * cE,
                                                b1 + (size_t)l * 4 * cE, nullptr,
                                                nullptr, ffnH, 4 * cE, cE, 1);
        // last layer: x (fp32) is never read again, only xH feeds the vocab GEMM
        float* xOut = (l == cL - 1) ? nullptr : x;
        gemm_f16<<<g512, 256, GEMM_SMEM_BYTES>>>(ffnH, W2H + (size_t)l * cE * 4 * cE,
                                                 b2 + (size_t)l * cE, x, xOut, xH, cE, 4 * cE, 0);
    }

    gemm_f16<<<dim3(cV / 128, cBS / 128), 256, GEMM_SMEM_BYTES>>>(
        xH, fcwH, fcb, nullptr, out, nullptr, cV, cE, 0);
}